// round 2
// baseline (speedup 1.0000x reference)
#include <cuda_runtime.h>
#include <math.h>

#define BB 16
#define TENC 512
#define DENC 512
#define NMEL 80
#define FRAME 240
#define TSTEPS 200
#define NFRAMES 199
#define PRE 256
#define ARNN 1024
#define ADIM 128
#define LK 31
#define GRID 148
#define NTHR 256

// ---------------- device scratch ----------------
__device__ float g_xraw[NFRAMES * BB * FRAME];
__device__ float g_h1[NFRAMES * BB * PRE];
__device__ float g_preT[TSTEPS * PRE * BB];      // [t][f][b]
__device__ float g_pm[BB * TENC * ADIM];         // [b][t][f]
__device__ float g_procloc[BB * TENC * ADIM];    // [b][t][f]
__device__ float g_haT[ARNN * BB];               // [j][b]
__device__ float g_caT[ARNN * BB];
__device__ float g_hdT[ARNN * BB];
__device__ float g_cdT[ARNN * BB];
__device__ float g_ctxT[DENC * BB];
__device__ float g_w[BB * TENC];
__device__ float g_wcum[BB * TENC];
__device__ float g_pA[8 * 4096 * BB];            // attn-gate k-split partials
__device__ float g_pD[16 * 4096 * BB];           // dec-gate k-split partials
__device__ float g_projC[FRAME * BB];            // proj ctx-part partial
__device__ unsigned g_cnt;
__device__ unsigned g_sense;

__device__ __forceinline__ float sigf(float x) { return 1.f / (1.f + expf(-x)); }

// ---------------- software grid barrier ----------------
__device__ __forceinline__ void gsync(unsigned ph) {
    __syncthreads();
    if (threadIdx.x == 0) {
        __threadfence();
        unsigned arr = atomicAdd(&g_cnt, 1u);
        if (arr == GRID - 1) {
            g_cnt = 0;
            __threadfence();
            atomicExch(&g_sense, ph);
        } else {
            while (atomicAdd(&g_sense, 0u) != ph) __nanosleep(32);
        }
    }
    __syncthreads();
}

// ---------------- init ----------------
__global__ void k_init() {
    int i = blockIdx.x * 256 + threadIdx.x;
    if (i == 0) { g_cnt = 0; g_sense = 0; }
    if (i < ARNN * BB) { g_haT[i] = 0.f; g_caT[i] = 0.f; g_hdT[i] = 0.f; g_cdT[i] = 0.f; }
    if (i < DENC * BB) g_ctxT[i] = 0.f;
    if (i < BB * TENC) { g_w[i] = 0.f; g_wcum[i] = 0.f; }
    if (i < PRE * BB) g_preT[i] = 0.f;   // prenet(go) == 0
}

// ---------------- gather decoder inputs into [m=d*16+b][240] ----------------
__global__ void k_gather(const float* __restrict__ din) {
    int idx = blockIdx.x * 256 + threadIdx.x;
    if (idx >= NFRAMES * BB * FRAME) return;
    int j = idx % FRAME;
    int m = idx / FRAME;
    int b = m % BB;
    int d = m / BB;
    int flat = d * FRAME + j;
    int col = flat % NMEL;
    int row = flat / NMEL;
    g_xraw[idx] = din[(b * NMEL + col) * 600 + row];
}

// ---------------- prologue tiled SGEMM: C[M][N] = A[M][K] * B[N][K]^T ----------------
__global__ void k_sgemm(const float* __restrict__ A, const float* __restrict__ Bw,
                        float* __restrict__ C, int M, int N, int K, int relu, int mode) {
    __shared__ float As[16][68];
    __shared__ float Bs[16][68];
    int m0 = blockIdx.x * 64, n0 = blockIdx.y * 64;
    int tx = threadIdx.x;
    int tr = tx >> 4, tc = tx & 15;
    float acc[4][4] = {};
    for (int k0 = 0; k0 < K; k0 += 16) {
        for (int i = tx; i < 1024; i += 256) {
            int mm = i >> 4, kk = i & 15;
            int m = m0 + mm, k = k0 + kk;
            As[kk][mm] = (m < M) ? A[(size_t)m * K + k] : 0.f;
            int n = n0 + mm;
            Bs[kk][mm] = (n < N) ? Bw[(size_t)n * K + k] : 0.f;
        }
        __syncthreads();
#pragma unroll
        for (int kk = 0; kk < 16; kk++) {
            float4 a4 = *(const float4*)&As[kk][tr * 4];
            float4 b4 = *(const float4*)&Bs[kk][tc * 4];
            float a_[4] = {a4.x, a4.y, a4.z, a4.w};
            float b_[4] = {b4.x, b4.y, b4.z, b4.w};
#pragma unroll
            for (int r = 0; r < 4; r++)
#pragma unroll
                for (int c = 0; c < 4; c++) acc[r][c] += a_[r] * b_[c];
        }
        __syncthreads();
    }
    for (int r = 0; r < 4; r++)
        for (int c = 0; c < 4; c++) {
            int m = m0 + tr * 4 + r, n = n0 + tc * 4 + c;
            if (m < M && n < N) {
                float v = acc[r][c];
                if (relu) v = fmaxf(v, 0.f);
                if (mode == 0) C[(size_t)m * N + n] = v;
                else {
                    int d = m >> 4, b = m & 15;
                    C[((d + 1) * PRE + n) * BB + b] = v;
                }
            }
        }
}

// ---------------- gate GEMM segment (activations via L2-coherent loads) ----------------
__device__ __forceinline__ void gseg(const float* __restrict__ wp, int wstr,
                                     const float* __restrict__ ap,
                                     int segstart, int seglen, int kbeg, int kend,
                                     int row0, int b0, float acc[4][4]) {
    int ks = max(kbeg, segstart);
    int ke = min(kend, segstart + seglen);
    for (int k = ks; k < ke; k += 4) {
        int kl = k - segstart;
        float4 av0 = __ldcg((const float4*)(ap + (kl + 0) * BB + b0));
        float4 av1 = __ldcg((const float4*)(ap + (kl + 1) * BB + b0));
        float4 av2 = __ldcg((const float4*)(ap + (kl + 2) * BB + b0));
        float4 av3 = __ldcg((const float4*)(ap + (kl + 3) * BB + b0));
#pragma unroll
        for (int r = 0; r < 4; r++) {
            float4 wv = *(const float4*)(wp + (size_t)(row0 + r) * wstr + kl);
            acc[r][0] += wv.x * av0.x + wv.y * av1.x + wv.z * av2.x + wv.w * av3.x;
            acc[r][1] += wv.x * av0.y + wv.y * av1.y + wv.z * av2.y + wv.w * av3.y;
            acc[r][2] += wv.x * av0.z + wv.y * av1.z + wv.z * av2.z + wv.w * av3.z;
            acc[r][3] += wv.x * av0.w + wv.y * av1.w + wv.z * av2.w + wv.w * av3.w;
        }
    }
}

__device__ __forceinline__ void gate_unit(
    const float* w0, int s0, const float* a0, int l0,
    const float* w1, int s1, const float* a1, int l1,
    const float* w2, int s2, const float* a2, int l2,
    float* part, int rowbase, int kbeg, int kend, int tid)
{
    int row0 = rowbase + (tid >> 2) * 4;
    int b0 = (tid & 3) * 4;
    float acc[4][4] = {};
    gseg(w0, s0, a0, 0, l0, kbeg, kend, row0, b0, acc);
    if (l1) gseg(w1, s1, a1, l0, l1, kbeg, kend, row0, b0, acc);
    if (l2) gseg(w2, s2, a2, l0 + l1, l2, kbeg, kend, row0, b0, acc);
#pragma unroll
    for (int r = 0; r < 4; r++)
#pragma unroll
        for (int c = 0; c < 4; c++)
            part[(size_t)(row0 + r) * BB + b0 + c] = acc[r][c];
}

// ---------------- LSTM cell element (reduces k-split partials) ----------------
__device__ __forceinline__ void cell(const float* part, int nslots,
                                     const float* bih, const float* bhh,
                                     float* hT, float* cT, int i) {
    int b = i & 15, j = i >> 4;
    float g[4];
#pragma unroll
    for (int gi = 0; gi < 4; gi++) {
        int row = gi * 1024 + j;
        float s = bih[row] + bhh[row];
        for (int sl = 0; sl < nslots; sl++)
            s += __ldcg(&part[((size_t)sl * 4096 + row) * BB + b]);
        g[gi] = s;
    }
    float c = sigf(g[1]) * __ldcg(&cT[i]) + sigf(g[0]) * tanhf(g[2]);
    float h = sigf(g[3]) * tanhf(c);
    cT[i] = c;
    hT[i] = h;
}

// ---------------- location conv + dense unit (b, 32-wide t chunk) ----------------
__device__ void loc_unit(int b, int tc, const float* __restrict__ lw,
                         const float* __restrict__ ld_, float* sh, int tid) {
    float* win = sh;          // [2][64]
    float* locs = sh + 128;   // [32][33]
    int t0 = tc * 32;
    if (tid < 128) {
        int ch = tid >> 6, idx = tid & 63;
        int tt = t0 - 15 + idx;
        bool ok = (tt >= 0 && tt < TENC && idx < 62);
        const float* src = ch ? g_wcum : g_w;
        win[ch * 64 + idx] = ok ? __ldcg(&src[b * TENC + tt]) : 0.f;
    }
    __syncthreads();
    for (int i = tid; i < 1024; i += NTHR) {
        int c = i >> 5, tt = i & 31;
        float acc = 0.f;
#pragma unroll
        for (int ch = 0; ch < 2; ch++)
#pragma unroll
            for (int kk = 0; kk < LK; kk++)
                acc += win[ch * 64 + tt + kk] * lw[c * 62 + ch * LK + kk];
        locs[c * 33 + tt] = acc;
    }
    __syncthreads();
    int f = tid & 127, th = tid >> 7;
    float ldr[32];
#pragma unroll
    for (int c = 0; c < 32; c++) ldr[c] = ld_[f * 32 + c];
    for (int tt = th * 16; tt < th * 16 + 16; tt++) {
        float acc = 0.f;
#pragma unroll
        for (int c = 0; c < 32; c++) acc += locs[c * 33 + tt] * ldr[c];
        g_procloc[((size_t)(b * TENC + t0 + tt)) * ADIM + f] = acc;
    }
    __syncthreads();
}

// ---------------- the persistent megakernel ----------------
__global__ void __launch_bounds__(NTHR) k_mega(
    const float* __restrict__ memory, const int* __restrict__ mlen,
    const float* __restrict__ aw_ih, const float* __restrict__ aw_hh,
    const float* __restrict__ ab_ih, const float* __restrict__ ab_hh,
    const float* __restrict__ dw_ih, const float* __restrict__ dw_hh,
    const float* __restrict__ db_ih, const float* __restrict__ db_hh,
    const float* __restrict__ Wq, const float* __restrict__ v_att,
    const float* __restrict__ lconv, const float* __restrict__ ldense,
    const float* __restrict__ proj_w, const float* __restrict__ proj_b,
    float* __restrict__ out_mel, float* __restrict__ out_align)
{
    __shared__ float sh[1184];
    int cta = blockIdx.x, tid = threadIdx.x;
    unsigned ph = 0;

    for (int t = 0; t <= TSTEPS; t++) {
        // ================= P1: proj-finish(t-1) + loc + attn-gate partials =========
        if (t > 0 && cta < 30 && tid < 128) {
            int r = cta * 8 + (tid >> 4), b = tid & 15;
            const float* wr = proj_w + (size_t)r * 1536;
            float acc = 0.f;
#pragma unroll 4
            for (int k = 0; k < 1024; k += 4) {
                float4 wv = *(const float4*)(wr + k);
                acc += wv.x * __ldcg(&g_hdT[(k + 0) * BB + b]) + wv.y * __ldcg(&g_hdT[(k + 1) * BB + b]) +
                       wv.z * __ldcg(&g_hdT[(k + 2) * BB + b]) + wv.w * __ldcg(&g_hdT[(k + 3) * BB + b]);
            }
            acc += __ldcg(&g_projC[r * BB + b]) + proj_b[r];
            int flat = (t - 1) * FRAME + r;
            int u = flat / NMEL, m = flat % NMEL;
            out_mel[(size_t)b * (NMEL * 600) + m * 600 + u] = acc;
        }
        if (t == TSTEPS) break;

        if (cta < 128) {
            int rc = cta >> 3, kc = cta & 7;
            gate_unit(aw_ih, 768, g_preT + (size_t)t * PRE * BB, 256,
                      aw_ih + 256, 768, g_ctxT, 512,
                      aw_hh, 1024, g_haT, 1024,
                      g_pA + (size_t)kc * 4096 * BB, rc * 256, kc * 224, kc * 224 + 224, tid);
            loc_unit(cta >> 4, cta & 15, lconv, ldense, sh, tid);
        } else {
            for (int u = 128 + (cta - 128); u < 256; u += 20)
                loc_unit(u >> 4, u & 15, lconv, ldense, sh, tid);
        }
        gsync(++ph);

        // ================= P2: attention LSTM cell ================================
        if (cta < 64) cell(g_pA, 8, ab_ih, ab_hh, g_haT, g_caT, cta * NTHR + tid);
        gsync(++ph);

        // ================= P3: attention chain (16 CTAs) || dec-gate h-parts =====
        if (cta < 128) {
            int rc = cta >> 3, kc = cta & 7;
            gate_unit(dw_ih, 1536, g_haT, 1024,
                      dw_hh, 1024, g_hdT, 1024,
                      (const float*)0, 0, (const float*)0, 0,
                      g_pD + (size_t)kc * 4096 * BB, rc * 256, kc * 256, kc * 256 + 256, tid);
        } else if (cta >= 132) {
            int b = cta - 132;
            // --- q = h_a @ Wq^T (split K over 2 halves) ---
            {
                int f = tid & 127, half = tid >> 7;
                const float* wr = Wq + (size_t)f * ARNN + half * 512;
                float acc = 0.f;
#pragma unroll 4
                for (int k = 0; k < 512; k += 4) {
                    float4 wv = *(const float4*)(wr + k);
                    int kg = half * 512 + k;
                    acc += wv.x * __ldcg(&g_haT[(kg + 0) * BB + b]) + wv.y * __ldcg(&g_haT[(kg + 1) * BB + b]) +
                           wv.z * __ldcg(&g_haT[(kg + 2) * BB + b]) + wv.w * __ldcg(&g_haT[(kg + 3) * BB + b]);
                }
                sh[256 + tid] = acc;
            }
            __syncthreads();
            if (tid < 128) {
                sh[tid] = sh[256 + tid] + sh[384 + tid];   // qs
                sh[128 + tid] = v_att[tid];                // vs
            }
            __syncthreads();
            // --- energies + mask ---
            int L = mlen[b];
            float ev[2];
#pragma unroll
            for (int it = 0; it < 2; it++) {
                int tt = tid + it * 256;
                const float* pl = &g_procloc[((size_t)b * TENC + tt) * ADIM];
                const float* pv = &g_pm[((size_t)b * TENC + tt) * ADIM];
                float acc = 0.f;
                for (int f = 0; f < ADIM; f += 4) {
                    float4 a = __ldcg((const float4*)(pl + f));
                    float4 p = *(const float4*)(pv + f);
                    acc += sh[128 + f + 0] * tanhf(sh[f + 0] + a.x + p.x);
                    acc += sh[128 + f + 1] * tanhf(sh[f + 1] + a.y + p.y);
                    acc += sh[128 + f + 2] * tanhf(sh[f + 2] + a.z + p.z);
                    acc += sh[128 + f + 3] * tanhf(sh[f + 3] + a.w + p.w);
                }
                ev[it] = (tt >= L) ? -1e9f : acc;
            }
            // --- softmax (block reduce over 512) ---
            sh[256 + tid] = fmaxf(ev[0], ev[1]);
            __syncthreads();
            for (int s = 128; s > 0; s >>= 1) {
                if (tid < s) sh[256 + tid] = fmaxf(sh[256 + tid], sh[256 + tid + s]);
                __syncthreads();
            }
            float mx = sh[256];
            __syncthreads();
            float ex0 = expf(ev[0] - mx), ex1 = expf(ev[1] - mx);
            sh[256 + tid] = ex0 + ex1;
            __syncthreads();
            for (int s = 128; s > 0; s >>= 1) {
                if (tid < s) sh[256 + tid] += sh[256 + tid + s];
                __syncthreads();
            }
            float inv = 1.f / sh[256];
            {
                int tt = tid;
                float wv = ex0 * inv;
                g_w[b * TENC + tt] = wv;
                g_wcum[b * TENC + tt] = __ldcg(&g_wcum[b * TENC + tt]) + wv;
                out_align[((size_t)b * TSTEPS + t) * TENC + tt] = wv;
                tt = tid + 256;
                wv = ex1 * inv;
                g_w[b * TENC + tt] = wv;
                g_wcum[b * TENC + tt] = __ldcg(&g_wcum[b * TENC + tt]) + wv;
                out_align[((size_t)b * TSTEPS + t) * TENC + tt] = wv;
            }
        }
        gsync(++ph);

        // ================= P4: context = w @ memory ===============================
        if (cta < 128) {
            int b = cta >> 3, d0 = (cta & 7) * 64;
            for (int i = tid; i < TENC; i += NTHR) sh[i] = __ldcg(&g_w[b * TENC + i]);
            __syncthreads();
            int dd = tid & 63, tq = tid >> 6;
            const float* mb = memory + ((size_t)b * TENC) * DENC + d0 + dd;
            float acc = 0.f;
            for (int tt = tq * 128; tt < tq * 128 + 128; tt++)
                acc += sh[tt] * mb[(size_t)tt * DENC];
            sh[512 + tid] = acc;
            __syncthreads();
            if (tid < 64) {
                float s = sh[512 + tid] + sh[576 + tid] + sh[640 + tid] + sh[704 + tid];
                g_ctxT[(d0 + tid) * BB + b] = s;
            }
            __syncthreads();
        }
        gsync(++ph);

        // ================= P5: dec-gate ctx-part + proj ctx-part ==================
        if (cta < 128) {
            int rc = cta >> 3, kc = cta & 7;
            gate_unit(dw_ih + 1024, 1536, g_ctxT, 512,
                      (const float*)0, 0, (const float*)0, 0,
                      (const float*)0, 0, (const float*)0, 0,
                      g_pD + (size_t)(8 + kc) * 4096 * BB, rc * 256, kc * 64, kc * 64 + 64, tid);
        } else if (tid < 192) {
            int r = (cta - 128) * 12 + (tid >> 4), b = tid & 15;
            const float* wr = proj_w + (size_t)r * 1536 + 1024;
            float acc = 0.f;
#pragma unroll 4
            for (int k = 0; k < 512; k += 4) {
                float4 wv = *(const float4*)(wr + k);
                acc += wv.x * __ldcg(&g_ctxT[(k + 0) * BB + b]) + wv.y * __ldcg(&g_ctxT[(k + 1) * BB + b]) +
                       wv.z * __ldcg(&g_ctxT[(k + 2) * BB + b]) + wv.w * __ldcg(&g_ctxT[(k + 3) * BB + b]);
            }
            g_projC[r * BB + b] = acc;
        }
        gsync(++ph);

        // ================= P6: decoder LSTM cell ==================================
        if (cta < 64) cell(g_pD, 16, db_ih, db_hh, g_hdT, g_cdT, cta * NTHR + tid);
        gsync(++ph);
    }
}

// ---------------- launch ----------------
extern "C" void kernel_launch(void* const* d_in, const int* in_sizes, int n_in,
                              void* d_out, int out_size) {
    const float* memory = (const float*)d_in[0];
    const float* dec_in = (const float*)d_in[1];
    const int*   mlen   = (const int*)d_in[2];
    const float* pw1    = (const float*)d_in[3];
    const float* pw2    = (const float*)d_in[4];
    const float* aw_ih  = (const float*)d_in[5];
    const float* aw_hh  = (const float*)d_in[6];
    const float* ab_ih  = (const float*)d_in[7];
    const float* ab_hh  = (const float*)d_in[8];
    const float* dw_ih  = (const float*)d_in[9];
    const float* dw_hh  = (const float*)d_in[10];
    const float* db_ih  = (const float*)d_in[11];
    const float* db_hh  = (const float*)d_in[12];
    const float* Wq     = (const float*)d_in[13];
    const float* Wm     = (const float*)d_in[14];
    const float* v_att  = (const float*)d_in[15];
    const float* lconv  = (const float*)d_in[16];
    const float* ldense = (const float*)d_in[17];
    const float* proj_w = (const float*)d_in[18];
    const float* proj_b = (const float*)d_in[19];

    float* out = (float*)d_out;
    float* align_out = out + (size_t)BB * NMEL * 600;

    float *s_xraw, *s_h1, *s_preT, *s_pm;
    cudaGetSymbolAddress((void**)&s_xraw, g_xraw);
    cudaGetSymbolAddress((void**)&s_h1, g_h1);
    cudaGetSymbolAddress((void**)&s_preT, g_preT);
    cudaGetSymbolAddress((void**)&s_pm, g_pm);

    k_init<<<256, 256>>>();
    k_gather<<<(NFRAMES * BB * FRAME + 255) / 256, 256>>>(dec_in);
    k_sgemm<<<dim3(50, 4), 256>>>(s_xraw, pw1, s_h1, NFRAMES * BB, PRE, FRAME, 1, 0);
    k_sgemm<<<dim3(50, 4), 256>>>(s_h1, pw2, s_preT, NFRAMES * BB, PRE, PRE, 1, 1);
    k_sgemm<<<dim3(128, 2), 256>>>(memory, Wm, s_pm, BB * TENC, ADIM, DENC, 0, 0);

    k_mega<<<GRID, NTHR>>>(memory, mlen,
                           aw_ih, aw_hh, ab_ih, ab_hh,
                           dw_ih, dw_hh, db_ih, db_hh,
                           Wq, v_att, lconv, ldense, proj_w, proj_b,
                           out, align_out);
}